// round 9
// baseline (speedup 1.0000x reference)
#include <cuda_runtime.h>
#include <math.h>

#define BATCH 8
#define CINC 64
#define COUTC 64
#define HDIM 128
#define WDIM 128
#define NPIX (HDIM*WDIM)          // 16384
#define NHEADS 4
#define CRED 32
#define TOT (BATCH*NPIX)          // 131072
#define KDIM (NHEADS*CRED)        // 128

typedef unsigned long long u64;

// packed fp32x2 helpers (Blackwell FFMA2 — only reachable via PTX)
#define FMA2(acc, a, b) \
    asm("fma.rn.f32x2 %0, %1, %2, %0;" : "+l"(acc) : "l"(a), "l"(b))
#define PACK_DUP(dst, f) \
    asm("mov.b64 %0, {%1, %1};" : "=l"(dst) : "r"(__float_as_uint(f)))
#define PACK2(dst, lo, hi) \
    asm("mov.b64 %0, {%1, %2};" : "=l"(dst) : "r"(__float_as_uint(lo)), "r"(__float_as_uint(hi)))
#define UNPACK2(lo, hi, src) \
    asm("mov.b64 {%0, %1}, %2;" : "=r"(lo), "=r"(hi) : "l"(src))

// -------- device scratch (no allocation allowed in kernel_launch) --------
__device__ float g_xr[(size_t)TOT*CRED];            // [B*N][32] node-major
__device__ float g_as[(size_t)TOT*NHEADS];
__device__ float g_ad[(size_t)TOT*NHEADS];
__device__ float g_out[(size_t)TOT*COUTC];          // [B][64][N] channel-major
__device__ float g_M[COUTC*KDIM];                   // [o][k] row-major
__device__ float g_wrb[COUTC];
__device__ float g_chsum[COUTC];
__device__ float g_chsq[COUTC];

// ------------- A: xr = w_reduce @ x + attention logits (+ folded kP) -----
// Each block computes pq locally; block 0 additionally folds M/wrb and
// zeroes BN accumulators (kB12 only starts after the full kA grid).
__global__ void __launch_bounds__(256) kA(const float* __restrict__ x,
                                          const float* __restrict__ w_reduce,
                                          const float* __restrict__ w_lin,
                                          const float* __restrict__ att_src,
                                          const float* __restrict__ att_dst,
                                          const float* __restrict__ b_gat,
                                          const float* __restrict__ w_restore) {
    __shared__ u64   wrp[(CRED/2)*CINC];  // packed channel-pair weights (8 KB)
    __shared__ float pq[2*NHEADS*CRED];
    __shared__ float xt[256*33];          // padded transpose buffer (33.8 KB)
    int t = threadIdx.x;

    for (int f = t; f < (CRED/2)*CINC; f += 256) {
        int c2 = f >> 6, cin = f & 63;
        u64 p;
        PACK2(p, w_reduce[(2*c2)*CINC + cin], w_reduce[(2*c2+1)*CINC + cin]);
        wrp[f] = p;
    }
    {   // pq computed per-block (8K MACs, trivial): p_h = W_h^T att_src[h]
        int which = t >> 7;
        int hc = t & 127;
        int h = hc >> 5, c = hc & 31;
        const float* att = which ? att_dst : att_src;
        float s = 0.f;
        #pragma unroll 8
        for (int cr = 0; cr < CRED; cr++)
            s += att[h*CRED+cr] * w_lin[(h*CRED+cr)*CRED + c];
        pq[t] = s;
    }
    if (blockIdx.x == 0) {   // folded kP: M, wrb, BN-acc zero
        for (int idx = t; idx < COUTC*KDIM; idx += 256) {
            int o = idx >> 7, k = idx & 127, h = k >> 5, c = k & 31;
            float s = 0.f;
            #pragma unroll 8
            for (int cr = 0; cr < CRED; cr++)
                s += w_restore[o*CRED+cr] * w_lin[(h*CRED+cr)*CRED + c];
            g_M[idx] = 0.25f * s;         // head-mean folded in
        }
        if (t < COUTC) {
            float s = 0.f;
            #pragma unroll 8
            for (int c = 0; c < CRED; c++) s += w_restore[t*CRED+c] * b_gat[c];
            g_wrb[t] = s;
            g_chsum[t] = 0.f;
            g_chsq[t]  = 0.f;
        }
    }
    __syncthreads();

    int gid = blockIdx.x * 256 + t;       // 0..TOT-1
    int b = gid >> 14;
    int pix = gid & (NPIX-1);
    const float* xb = x + ((size_t)b*CINC)*NPIX + pix;

    u64 acc2[CRED/2];
    #pragma unroll
    for (int c2 = 0; c2 < CRED/2; c2++) acc2[c2] = 0ull;

    #pragma unroll 4
    for (int cin = 0; cin < CINC; cin++) {
        float xv = xb[(size_t)cin*NPIX];
        u64 xp; PACK_DUP(xp, xv);
        #pragma unroll
        for (int c2 = 0; c2 < CRED/2; c2++)
            FMA2(acc2[c2], wrp[c2*CINC + cin], xp);
    }

    float acc[CRED];
    #pragma unroll
    for (int c2 = 0; c2 < CRED/2; c2++) {
        unsigned lo, hi; UNPACK2(lo, hi, acc2[c2]);
        acc[2*c2]   = __uint_as_float(lo);    // low lane = even channel
        acc[2*c2+1] = __uint_as_float(hi);
    }

    float asv[NHEADS], adv[NHEADS];
    #pragma unroll
    for (int h = 0; h < NHEADS; h++) {
        float ps = 0.f, qs = 0.f;
        #pragma unroll
        for (int c = 0; c < CRED; c++) {
            ps += pq[h*CRED+c]       * acc[c];
            qs += pq[128 + h*CRED+c] * acc[c];
        }
        asv[h] = ps; adv[h] = qs;
    }
    *(float4*)&g_as[(size_t)gid*NHEADS] = make_float4(asv[0],asv[1],asv[2],asv[3]);
    *(float4*)&g_ad[(size_t)gid*NHEADS] = make_float4(adv[0],adv[1],adv[2],adv[3]);

    // ---- coalesced xr writeback via padded smem transpose ----
    // STS: addr t*33+c -> bank (t+c)%32, conflict-free.
    #pragma unroll
    for (int c = 0; c < CRED; c++) xt[t*33 + c] = acc[c];
    __syncthreads();
    // Reader: warp covers 32 consecutive floats of one row -> full 128B lines.
    int gpix = blockIdx.x * 256;
    for (int f = t; f < 256*CRED; f += 256) {
        int row = f >> 5, c = f & 31;
        g_xr[((size_t)(gpix + row))*CRED + c] = xt[row*33 + c];
    }
}

// ====== B12: fused GAT aggregation + restore GEMM + residual + BN-stats ==
// One block per (batch, grid-row): 128 pixels. 4-neighborhood of a grid row
// lives in rows i-1, i, i+1. xr neighbor rows are read DIRECTLY from global
// (warp-coalesced 128B rows, L2-resident) so smem fits 2 CTAs/SM and phases
// of co-resident CTAs overlap.
//
// Dynamic smem layout (floats):
//   Ms  [128][68]   @ 0       (8704)   M transposed: [k][o], padded rows
//   Ss  [128][132]  @ 8704    (16896)  S: [k][p], padded rows
//   As3 [3][128][4] @ 25600   (1536)   a_src rows i-1,i,i+1
//   Ad4 [128][4]    @ 27136   (512)    a_dst row i
//   wrb [64]        @ 27648   (64)
// total 27712 floats = 110848 B  (x2 = 221.7 KB <= 228 KB/SM)
#define SM_MS   0
#define SM_SS   8704
#define SM_AS   25600
#define SM_AD   27136
#define SM_WRB  27648
#define SM_FLOATS 27712

__global__ void __launch_bounds__(256, 2) kB12(const float* __restrict__ x) {
    extern __shared__ float sm[];
    float* Ms  = sm + SM_MS;
    float* Ss  = sm + SM_SS;
    float* As3 = sm + SM_AS;
    float* Ad4 = sm + SM_AD;
    float* wrbs= sm + SM_WRB;

    int t = threadIdx.x;
    int b = blockIdx.x >> 7;
    int i = blockIdx.x & 127;             // grid row
    int gbase = b << 14;

    // ---- stage M (transposed) and wrb ----
    for (int f = t; f < COUTC*KDIM; f += 256)
        Ms[(f & 127)*68 + (f >> 7)] = g_M[f];
    if (t < COUTC) wrbs[t] = g_wrb[t];

    // ---- stage a_src rows i-1,i,i+1 and a_dst row i ----
    for (int f = t; f < 3*128; f += 256) {
        int r = f >> 7, j = f & 127;
        int gi = i - 1 + r;
        float4 v = make_float4(0.f,0.f,0.f,0.f);
        if (gi >= 0 && gi < HDIM)
            v = *(const float4*)&g_as[((size_t)(gbase + gi*WDIM + j))*NHEADS];
        *(float4*)&As3[(r*128 + j)*4] = v;
    }
    if (t < 128)
        *(float4*)&Ad4[t*4] = *(const float4*)&g_ad[((size_t)(gbase + i*WDIM + t))*NHEADS];
    __syncthreads();

    // ---- phase 2: softmax + weighted neighbor sums -> Ss[k][p] ----
    // No max-subtraction: softmax is shift-invariant and logits are O(1-10),
    // far from fp32 exp overflow. xr rows read straight from g_xr
    // (coalesced 128B warp loads, L2-resident).
    {
        int w = t >> 5, lane = t & 31;
        bool up = (i > 0), dn = (i < HDIM-1);
        for (int jb = 0; jb < 4; jb++) {
            float sjh[NHEADS][4];
            #pragma unroll
            for (int jq = 0; jq < 4; jq++) {
                int j = w*16 + jb*4 + jq;
                bool lf = (j > 0), rt = (j < WDIM-1);
                // u: 0=self(r1,j) 1=up(r0,j) 2=down(r2,j) 3=left 4=right
                int  ru[5] = {1, 0, 2, 1, 1};
                int  ju[5] = {j, j, j, (j>0? j-1 : j), (j<WDIM-1? j+1 : j)};
                bool vl[5] = {true, up, dn, lf, rt};

                // kick off the 5 xr loads early (independent, latency hidden)
                float xv[5];
                #pragma unroll
                for (int u = 0; u < 5; u++) {
                    int gi = i - 1 + ru[u];
                    xv[u] = vl[u]
                        ? g_xr[((size_t)(gbase + gi*WDIM + ju[u]))*CRED + lane]
                        : 0.f;
                }

                float ex[5][NHEADS], den[NHEADS];
                #pragma unroll
                for (int h = 0; h < NHEADS; h++) {
                    float adh = Ad4[j*4 + h];
                    float d = 0.f;
                    #pragma unroll
                    for (int u = 0; u < 5; u++) {
                        float ev = As3[(ru[u]*128 + ju[u])*4 + h] + adh;
                        ev = ev > 0.f ? ev : 0.2f*ev;   // leaky_relu(0.2)
                        float xx = vl[u] ? __expf(ev) : 0.f;
                        ex[u][h] = xx; d += xx;
                    }
                    den[h] = 1.f / d;
                }
                #pragma unroll
                for (int h = 0; h < NHEADS; h++) {
                    float s = 0.f;
                    #pragma unroll
                    for (int u = 0; u < 5; u++) s += ex[u][h] * xv[u];
                    sjh[h][jq] = s * den[h];
                }
            }
            int j0 = w*16 + jb*4;
            #pragma unroll
            for (int h = 0; h < NHEADS; h++)
                *(float4*)&Ss[(h*CRED + lane)*132 + j0] =
                    make_float4(sjh[h][0], sjh[h][1], sjh[h][2], sjh[h][3]);
        }
    }
    __syncthreads();

    // ---- phase 3: GEMM via packed FFMA2. Lanes = adjacent output channels:
    //      acc2[op][ip] = (out[o0+2op], out[o0+2op+1]) at pixel p0+ip.
    //      M pairs come packed straight from smem (consecutive o).
    int po = t & 31, oo = t >> 5;
    int p0 = po*4, o0 = oo*8;
    u64 acc2[4][4];
    #pragma unroll
    for (int a0 = 0; a0 < 4; a0++)
        #pragma unroll
        for (int a1 = 0; a1 < 4; a1++) acc2[a0][a1] = 0ull;

    #pragma unroll 1
    for (int k0 = 0; k0 < KDIM; k0 += 8) {
        #pragma unroll
        for (int kk = 0; kk < 8; kk++) {
            int k = k0 + kk;
            const ulonglong2* mr = (const ulonglong2*)&Ms[k*68 + o0]; // 16B aligned
            ulonglong2 ma = mr[0], mb = mr[1];
            u64 mp[4] = {ma.x, ma.y, mb.x, mb.y};
            float4 sv = *(const float4*)&Ss[k*132 + p0];
            u64 sp[4];
            PACK_DUP(sp[0], sv.x); PACK_DUP(sp[1], sv.y);
            PACK_DUP(sp[2], sv.z); PACK_DUP(sp[3], sv.w);
            #pragma unroll
            for (int op = 0; op < 4; op++)
                #pragma unroll
                for (int ip = 0; ip < 4; ip++)
                    FMA2(acc2[op][ip], mp[op], sp[ip]);
        }
    }

    // unpack to scalar tile [8 o][4 p]
    float acc[8][4];
    #pragma unroll
    for (int op = 0; op < 4; op++)
        #pragma unroll
        for (int ip = 0; ip < 4; ip++) {
            unsigned lo, hi; UNPACK2(lo, hi, acc2[op][ip]);
            acc[2*op][ip]   = __uint_as_float(lo);   // low lane = even o offset
            acc[2*op+1][ip] = __uint_as_float(hi);
        }

    // ---- epilogue: +wrb +residual, store, per-channel BN partial sums ----
    float csum[8], csq[8];
    #pragma unroll
    for (int io = 0; io < 8; io++) {
        int o = o0 + io;
        size_t off = (((size_t)b*COUTC + o) << 14) + i*WDIM + p0;
        float4 xv = *(const float4*)&x[off];
        float wb = wrbs[o];
        float4 r;
        r.x = acc[io][0] + wb + xv.x;
        r.y = acc[io][1] + wb + xv.y;
        r.z = acc[io][2] + wb + xv.z;
        r.w = acc[io][3] + wb + xv.w;
        *(float4*)&g_out[off] = r;
        csum[io] = r.x + r.y + r.z + r.w;
        csq[io]  = r.x*r.x + r.y*r.y + r.z*r.z + r.w*r.w;
    }
    // warp owns channels o0..o0+7 exclusively over all 128 pixels of this row
    #pragma unroll
    for (int io = 0; io < 8; io++) {
        #pragma unroll
        for (int off = 16; off > 0; off >>= 1) {
            csum[io] += __shfl_down_sync(0xffffffffu, csum[io], off);
            csq[io]  += __shfl_down_sync(0xffffffffu, csq[io],  off);
        }
    }
    if (po == 0) {
        #pragma unroll
        for (int io = 0; io < 8; io++) {
            atomicAdd(&g_chsum[o0+io], csum[io]);
            atomicAdd(&g_chsq[o0+io],  csq[io]);
        }
    }
}

// ------------------ D: normalize + affine + relu -------------------------
__global__ void __launch_bounds__(256) kD(const float* __restrict__ gamma,
                                          const float* __restrict__ beta,
                                          float* __restrict__ out) {
    size_t e4 = (size_t)blockIdx.x * 256 + threadIdx.x;   // float4 index
    size_t e = e4 * 4;
    int c = (int)((e >> 14) & 63);
    const float invcnt = 1.f / (float)(BATCH*NPIX);
    float mean = g_chsum[c] * invcnt;
    float var  = g_chsq[c] * invcnt - mean*mean;
    float inv  = rsqrtf(var + 1e-5f) * gamma[c];
    float sh   = beta[c] - mean * inv;
    float4 v = *(const float4*)&g_out[e];
    float4 r;
    r.x = fmaxf(v.x*inv + sh, 0.f);
    r.y = fmaxf(v.y*inv + sh, 0.f);
    r.z = fmaxf(v.z*inv + sh, 0.f);
    r.w = fmaxf(v.w*inv + sh, 0.f);
    *(float4*)&out[e] = r;
}

// -------------------------------------------------------------------------
extern "C" void kernel_launch(void* const* d_in, const int* in_sizes, int n_in,
                              void* d_out, int out_size) {
    const float* x         = (const float*)d_in[0];
    const float* w_reduce  = (const float*)d_in[1];
    const float* w_lin     = (const float*)d_in[2];
    const float* att_src   = (const float*)d_in[3];
    const float* att_dst   = (const float*)d_in[4];
    const float* b_gat     = (const float*)d_in[5];
    const float* w_restore = (const float*)d_in[6];
    const float* bn_gamma  = (const float*)d_in[7];
    const float* bn_beta   = (const float*)d_in[8];
    // d_in[9]=src, d_in[10]=dst : fixed 4-neighbor grid + self loops (implicit)
    float* out = (float*)d_out;

    // Idempotent, deterministic, not stream-ordered: safe under graph capture,
    // no static guards (harness forbids call-count-dependent behavior).
    cudaFuncSetAttribute(kB12, cudaFuncAttributeMaxDynamicSharedMemorySize,
                         SM_FLOATS * (int)sizeof(float));

    kA<<<TOT/256, 256>>>(x, w_reduce, w_lin, att_src, att_dst, b_gat, w_restore);
    kB12<<<TOT/WDIM, 256, SM_FLOATS*sizeof(float)>>>(x);
    kD<<<(size_t)(TOT)*COUTC/(256*4), 256>>>(bn_gamma, bn_beta, out);
}

// round 11
// speedup vs baseline: 1.2889x; 1.2889x over previous
#include <cuda_runtime.h>
#include <math.h>

#define BATCH 8
#define CINC 64
#define COUTC 64
#define HDIM 128
#define WDIM 128
#define NPIX (HDIM*WDIM)          // 16384
#define NHEADS 4
#define CRED 32
#define TOT (BATCH*NPIX)          // 131072
#define KDIM (NHEADS*CRED)        // 128

typedef unsigned long long u64;

// packed fp32x2 helpers (Blackwell FFMA2 — only reachable via PTX)
#define FMA2(acc, a, b) \
    asm("fma.rn.f32x2 %0, %1, %2, %0;" : "+l"(acc) : "l"(a), "l"(b))
#define PACK_DUP(dst, f) \
    asm("mov.b64 %0, {%1, %1};" : "=l"(dst) : "r"(__float_as_uint(f)))
#define UNPACK2(lo, hi, src) \
    asm("mov.b64 {%0, %1}, %2;" : "=r"(lo), "=r"(hi) : "l"(src))

// -------- device scratch (no allocation allowed in kernel_launch) --------
__device__ float g_xr[(size_t)TOT*CRED];            // [B*N][32] node-major
__device__ float g_as[(size_t)TOT*NHEADS];
__device__ float g_ad[(size_t)TOT*NHEADS];
__device__ float g_out[(size_t)TOT*COUTC];          // [B][64][N] channel-major
__device__ float g_M[COUTC*KDIM];                   // [o][k] row-major
__device__ float g_wrb[COUTC];
__device__ float g_chsum[COUTC];
__device__ float g_chsq[COUTC];

// ------------- A: xr = W @ x as a register-tiled GEMM + logits -----------
// Block = 128 pixels of one batch image. GEMM: out[32 c][128 p] per block,
// thread tile 4c x 4p. Epilogue: xr tile transposed in smem -> logits +
// fully-coalesced writeback of g_xr / g_as / g_ad.
__global__ void __launch_bounds__(256, 3) kA(const float* __restrict__ x,
                                             const float* __restrict__ w_reduce,
                                             const float* __restrict__ w_lin,
                                             const float* __restrict__ att_src,
                                             const float* __restrict__ att_dst,
                                             const float* __restrict__ b_gat,
                                             const float* __restrict__ w_restore) {
    __shared__ float xs[64*132];     // x tile [cin][128p], stride 132 (33.8 KB)
    __shared__ float ws[64*36];      // W^T [cin][32c], stride 36 (9.2 KB)
    __shared__ float pqs[2*NHEADS*CRED];
    __shared__ float xrT[128*44];    // xr [p][32c], stride 44 (22.5 KB)

    int t = threadIdx.x;
    int b = blockIdx.x >> 7;                // 128 blocks per image
    int pix0 = (blockIdx.x & 127) << 7;

    // ---- stage W transposed: ws[cin][c] = w_reduce[c][cin] ----
    for (int f = t; f < CRED*CINC; f += 256) {
        int c = f >> 6, cin = f & 63;
        ws[cin*36 + c] = w_reduce[f];
    }
    // ---- pq per block: pq[h][c] = (W_h^T att)[c]  (8K MACs, trivial) ----
    {
        int which = t >> 7;                 // 0 -> p (att_src), 1 -> q (att_dst)
        int hc = t & 127;
        int h = hc >> 5, c = hc & 31;
        const float* att = which ? att_dst : att_src;
        float s = 0.f;
        #pragma unroll 8
        for (int cr = 0; cr < CRED; cr++)
            s += att[h*CRED+cr] * w_lin[(h*CRED+cr)*CRED + c];
        pqs[t] = s;
    }
    if (blockIdx.x == 0) {   // folded kP: M, wrb, BN-acc zero
        for (int idx = t; idx < COUTC*KDIM; idx += 256) {
            int o = idx >> 7, k = idx & 127, h = k >> 5, c = k & 31;
            float s = 0.f;
            #pragma unroll 8
            for (int cr = 0; cr < CRED; cr++)
                s += w_restore[o*CRED+cr] * w_lin[(h*CRED+cr)*CRED + c];
            g_M[idx] = 0.25f * s;           // head-mean folded in
        }
        if (t < COUTC) {
            float s = 0.f;
            #pragma unroll 8
            for (int c = 0; c < CRED; c++) s += w_restore[t*CRED+c] * b_gat[c];
            g_wrb[t] = s;
            g_chsum[t] = 0.f;
            g_chsq[t]  = 0.f;
        }
    }
    // ---- stage x tile [64 cin][128 p] (coalesced 512B per warp) ----
    {
        const float* xb = x + (((size_t)b*CINC) << 14) + pix0;
        for (int f = t; f < 2048; f += 256) {           // 2048 float4s
            int cin = f >> 5, p4 = f & 31;
            *(float4*)&xs[cin*132 + 4*p4] =
                *(const float4*)&xb[(((size_t)cin) << 14) + 4*p4];
        }
    }
    __syncthreads();

    // ---- GEMM 32x128x64: thread tile 4c x 4p ----
    int po = t & 31, co = t >> 5;
    int p0 = 4*po, c0 = 4*co;
    u64 acc2[2][4];                          // c-pairs x 4 px
    #pragma unroll
    for (int a0 = 0; a0 < 2; a0++)
        #pragma unroll
        for (int a1 = 0; a1 < 4; a1++) acc2[a0][a1] = 0ull;

    #pragma unroll 4
    for (int cin = 0; cin < CINC; cin++) {
        ulonglong2 wv = *(const ulonglong2*)&ws[cin*36 + c0];  // broadcast
        float4 xv = *(const float4*)&xs[cin*132 + p0];
        u64 xp[4];
        PACK_DUP(xp[0], xv.x); PACK_DUP(xp[1], xv.y);
        PACK_DUP(xp[2], xv.z); PACK_DUP(xp[3], xv.w);
        #pragma unroll
        for (int ip = 0; ip < 4; ip++) {
            FMA2(acc2[0][ip], wv.x, xp[ip]);
            FMA2(acc2[1][ip], wv.y, xp[ip]);
        }
    }

    // ---- store xr tile transposed: xrT[p][c0..c0+3] ----
    #pragma unroll
    for (int ip = 0; ip < 4; ip++) {
        unsigned l0, h0, l1, h1;
        UNPACK2(l0, h0, acc2[0][ip]);
        UNPACK2(l1, h1, acc2[1][ip]);
        *(float4*)&xrT[(p0+ip)*44 + c0] =
            make_float4(__uint_as_float(l0), __uint_as_float(h0),
                        __uint_as_float(l1), __uint_as_float(h1));
    }
    __syncthreads();

    // ---- logits: 2 threads per pixel (half 0 -> a_src, 1 -> a_dst) ----
    {
        int px = t & 127, half = t >> 7;
        const float* pqh = pqs + half*128;
        float a0 = 0.f, a1 = 0.f, a2 = 0.f, a3 = 0.f;
        #pragma unroll
        for (int k = 0; k < 8; k++) {
            float4 xv = *(const float4*)&xrT[px*44 + 4*k];
            int cb = 4*k;
            a0 += pqh[0*CRED+cb]*xv.x + pqh[0*CRED+cb+1]*xv.y
                + pqh[0*CRED+cb+2]*xv.z + pqh[0*CRED+cb+3]*xv.w;
            a1 += pqh[1*CRED+cb]*xv.x + pqh[1*CRED+cb+1]*xv.y
                + pqh[1*CRED+cb+2]*xv.z + pqh[1*CRED+cb+3]*xv.w;
            a2 += pqh[2*CRED+cb]*xv.x + pqh[2*CRED+cb+1]*xv.y
                + pqh[2*CRED+cb+2]*xv.z + pqh[2*CRED+cb+3]*xv.w;
            a3 += pqh[3*CRED+cb]*xv.x + pqh[3*CRED+cb+1]*xv.y
                + pqh[3*CRED+cb+2]*xv.z + pqh[3*CRED+cb+3]*xv.w;
        }
        size_t node = ((size_t)b << 14) + pix0 + px;
        float* dst = half ? g_ad : g_as;
        *(float4*)&dst[node*NHEADS] = make_float4(a0, a1, a2, a3);
    }

    // ---- xr writeback: full 128B lines per pixel row ----
    {
        int gpix = (b << 14) + pix0;
        for (int f = t; f < 1024; f += 256) {       // 128 px x 8 chunks
            int px = f >> 3, k = f & 7;
            *(float4*)&g_xr[((size_t)(gpix+px))*CRED + 4*k] =
                *(const float4*)&xrT[px*44 + 4*k];
        }
    }
}

// ====== B12: fused GAT aggregation + restore GEMM + residual + BN-stats ==
// One block per (batch, grid-row): 128 pixels.
// Phase 2a computes each node's softmax ONCE (512 (node,head) pairs across
// 256 threads) -> normalized alpha in smem; phase 2b does the weighted sums
// with broadcast alpha reads. This removes the 32x lane-redundant MUFU.EX2
// work of the previous version. Alpha overlays the Ms region; Ms/wrb are
// staged after phase 2b (M is only needed in phase 3).
//
// Dynamic smem layout (floats):
//   Ms  [128][68]   @ 0       (8704)   phase 3; ALSO Al[128][20] in phase 2
//   Ss  [128][132]  @ 8704    (16896)  S: [k][p], padded rows
//   As3 [3][128][4] @ 25600   (1536)   a_src rows i-1,i,i+1
//   Ad4 [128][4]    @ 27136   (512)    a_dst row i
//   wrb [64]        @ 27648   (64)
// total 27712 floats = 110848 B  (x2 = 221.7 KB <= 228 KB/SM)
#define SM_MS   0
#define SM_SS   8704
#define SM_AS   25600
#define SM_AD   27136
#define SM_WRB  27648
#define SM_FLOATS 27712

__global__ void __launch_bounds__(256, 2) kB12(const float* __restrict__ x) {
    extern __shared__ float sm[];
    float* Ms  = sm + SM_MS;
    float* Al  = sm + SM_MS;              // overlay: alpha [j][u][h], j*20+u*4+h
    float* Ss  = sm + SM_SS;
    float* As3 = sm + SM_AS;
    float* Ad4 = sm + SM_AD;
    float* wrbs= sm + SM_WRB;

    int t = threadIdx.x;
    int b = blockIdx.x >> 7;
    int i = blockIdx.x & 127;             // grid row
    int gbase = b << 14;

    // ---- stage a_src rows i-1,i,i+1 and a_dst row i ----
    for (int f = t; f < 3*128; f += 256) {
        int r = f >> 7, j = f & 127;
        int gi = i - 1 + r;
        float4 v = make_float4(0.f,0.f,0.f,0.f);
        if (gi >= 0 && gi < HDIM)
            v = *(const float4*)&g_as[((size_t)(gbase + gi*WDIM + j))*NHEADS];
        *(float4*)&As3[(r*128 + j)*4] = v;
    }
    if (t < 128)
        *(float4*)&Ad4[t*4] = *(const float4*)&g_ad[((size_t)(gbase + i*WDIM + t))*NHEADS];
    __syncthreads();

    // ---- phase 2a: per-(node,head) softmax, computed ONCE -> Al ----
    // 512 pairs over 256 threads. Normalized alpha stored, so 2b needs no den.
    {
        bool up = (i > 0), dn = (i < HDIM-1);
        #pragma unroll
        for (int it = 0; it < 2; it++) {
            int pair = t + it*256;
            int j = pair & 127, h = pair >> 7;       // h in 0..3
            bool lf = (j > 0), rt = (j < WDIM-1);
            int  ru[5] = {1, 0, 2, 1, 1};
            int  ju[5] = {j, j, j, (j>0? j-1 : j), (j<WDIM-1? j+1 : j)};
            bool vl[5] = {true, up, dn, lf, rt};
            float adh = Ad4[j*4 + h];
            float ex[5]; float d = 0.f;
            #pragma unroll
            for (int u = 0; u < 5; u++) {
                float ev = As3[(ru[u]*128 + ju[u])*4 + h] + adh;
                ev = ev > 0.f ? ev : 0.2f*ev;        // leaky_relu(0.2)
                float xx = vl[u] ? __expf(ev) : 0.f; // shift-free: |logit| small
                ex[u] = xx; d += xx;
            }
            float rd = 1.f / d;
            #pragma unroll
            for (int u = 0; u < 5; u++)
                Al[j*20 + u*4 + h] = ex[u] * rd;
        }
    }
    __syncthreads();

    // ---- phase 2b: weighted neighbor sums -> Ss[k][p] ----
    // Alpha via lane-uniform LDS.128 broadcast; xr rows via coalesced LDG.
    // j blocked by 4: one STS.128 per head per block, conflict-free.
    {
        int w = t >> 5, lane = t & 31;
        bool up = (i > 0), dn = (i < HDIM-1);
        for (int jb = 0; jb < 4; jb++) {
            float sjh[NHEADS][4];
            #pragma unroll
            for (int jq = 0; jq < 4; jq++) {
                int j = w*16 + jb*4 + jq;
                bool lf = (j > 0), rt = (j < WDIM-1);
                int  ru[5] = {1, 0, 2, 1, 1};
                int  ju[5] = {j, j, j, (j>0? j-1 : j), (j<WDIM-1? j+1 : j)};
                bool vl[5] = {true, up, dn, lf, rt};

                // 5 independent coalesced xr row loads (latency overlapped)
                float xv[5];
                #pragma unroll
                for (int u = 0; u < 5; u++) {
                    int gi = i - 1 + ru[u];
                    xv[u] = vl[u]
                        ? g_xr[((size_t)(gbase + gi*WDIM + ju[u]))*CRED + lane]
                        : 0.f;
                }
                // alpha: 5 broadcast float4 loads (invalid u have alpha 0)
                float4 al[5];
                #pragma unroll
                for (int u = 0; u < 5; u++)
                    al[u] = *(const float4*)&Al[j*20 + u*4];

                float s0 = 0.f, s1 = 0.f, s2 = 0.f, s3 = 0.f;
                #pragma unroll
                for (int u = 0; u < 5; u++) {
                    s0 += al[u].x * xv[u];
                    s1 += al[u].y * xv[u];
                    s2 += al[u].z * xv[u];
                    s3 += al[u].w * xv[u];
                }
                sjh[0][jq] = s0; sjh[1][jq] = s1;
                sjh[2][jq] = s2; sjh[3][jq] = s3;
            }
            int j0 = w*16 + jb*4;
            #pragma unroll
            for (int h = 0; h < NHEADS; h++)
                *(float4*)&Ss[(h*CRED + lane)*132 + j0] =
                    make_float4(sjh[h][0], sjh[h][1], sjh[h][2], sjh[h][3]);
        }
    }
    __syncthreads();

    // ---- stage M (transposed) and wrb (after alpha overlay is dead) ----
    for (int f = t; f < COUTC*KDIM; f += 256)
        Ms[(f & 127)*68 + (f >> 7)] = g_M[f];
    if (t < COUTC) wrbs[t] = g_wrb[t];
    __syncthreads();

    // ---- phase 3: GEMM via packed FFMA2. Lanes = adjacent output channels:
    //      acc2[op][ip] = (out[o0+2op], out[o0+2op+1]) at pixel p0+ip.
    int po = t & 31, oo = t >> 5;
    int p0 = po*4, o0 = oo*8;
    u64 acc2[4][4];
    #pragma unroll
    for (int a0 = 0; a0 < 4; a0++)
        #pragma unroll
        for (int a1 = 0; a1 < 4; a1++) acc2[a0][a1] = 0ull;

    #pragma unroll 1
    for (int k0 = 0; k0 < KDIM; k0 += 8) {
        #pragma unroll
        for (int kk = 0; kk < 8; kk++) {
            int k = k0 + kk;
            const ulonglong2* mr = (const ulonglong2*)&Ms[k*68 + o0]; // 16B aligned
            ulonglong2 ma = mr[0], mb = mr[1];
            u64 mp[4] = {ma.x, ma.y, mb.x, mb.y};
            float4 sv = *(const float4*)&Ss[k*132 + p0];
            u64 sp[4];
            PACK_DUP(sp[0], sv.x); PACK_DUP(sp[1], sv.y);
            PACK_DUP(sp[2], sv.z); PACK_DUP(sp[3], sv.w);
            #pragma unroll
            for (int op = 0; op < 4; op++)
                #pragma unroll
                for (int ip = 0; ip < 4; ip++)
                    FMA2(acc2[op][ip], mp[op], sp[ip]);
        }
    }

    // unpack to scalar tile [8 o][4 p]
    float acc[8][4];
    #pragma unroll
    for (int op = 0; op < 4; op++)
        #pragma unroll
        for (int ip = 0; ip < 4; ip++) {
            unsigned lo, hi; UNPACK2(lo, hi, acc2[op][ip]);
            acc[2*op][ip]   = __uint_as_float(lo);   // low lane = even o offset
            acc[2*op+1][ip] = __uint_as_float(hi);
        }

    // ---- epilogue: +wrb +residual, store, per-channel BN partial sums ----
    float csum[8], csq[8];
    #pragma unroll
    for (int io = 0; io < 8; io++) {
        int o = o0 + io;
        size_t off = (((size_t)b*COUTC + o) << 14) + i*WDIM + p0;
        float4 xv = *(const float4*)&x[off];
        float wb = wrbs[o];
        float4 r;
        r.x = acc[io][0] + wb + xv.x;
        r.y = acc[io][1] + wb + xv.y;
        r.z = acc[io][2] + wb + xv.z;
        r.w = acc[io][3] + wb + xv.w;
        *(float4*)&g_out[off] = r;
        csum[io] = r.x + r.y + r.z + r.w;
        csq[io]  = r.x*r.x + r.y*r.y + r.z*r.z + r.w*r.w;
    }
    // warp owns channels o0..o0+7 exclusively over all 128 pixels of this row
    #pragma unroll
    for (int io = 0; io < 8; io++) {
        #pragma unroll
        for (int off = 16; off > 0; off >>= 1) {
            csum[io] += __shfl_down_sync(0xffffffffu, csum[io], off);
            csq[io]  += __shfl_down_sync(0xffffffffu, csq[io],  off);
        }
    }
    if (po == 0) {
        #pragma unroll
        for (int io = 0; io < 8; io++) {
            atomicAdd(&g_chsum[o0+io], csum[io]);
            atomicAdd(&g_chsq[o0+io],  csq[io]);
        }
    }
}

// ------------------ D: normalize + affine + relu -------------------------
__global__ void __launch_bounds__(256) kD(const float* __restrict__ gamma,
                                          const float* __restrict__ beta,
                                          float* __restrict__ out) {
    size_t e4 = (size_t)blockIdx.x * 256 + threadIdx.x;   // float4 index
    size_t e = e4 * 4;
    int c = (int)((e >> 14) & 63);
    const float invcnt = 1.f / (float)(BATCH*NPIX);
    float mean = g_chsum[c] * invcnt;
    float var  = g_chsq[c] * invcnt - mean*mean;
    float inv  = rsqrtf(var + 1e-5f) * gamma[c];
    float sh   = beta[c] - mean * inv;
    float4 v = *(const float4*)&g_out[e];
    float4 r;
    r.x = fmaxf(v.x*inv + sh, 0.f);
    r.y = fmaxf(v.y*inv + sh, 0.f);
    r.z = fmaxf(v.z*inv + sh, 0.f);
    r.w = fmaxf(v.w*inv + sh, 0.f);
    *(float4*)&out[e] = r;
}

// -------------------------------------------------------------------------
extern "C" void kernel_launch(void* const* d_in, const int* in_sizes, int n_in,
                              void* d_out, int out_size) {
    const float* x         = (const float*)d_in[0];
    const float* w_reduce  = (const float*)d_in[1];
    const float* w_lin     = (const float*)d_in[2];
    const float* att_src   = (const float*)d_in[3];
    const float* att_dst   = (const float*)d_in[4];
    const float* b_gat     = (const float*)d_in[5];
    const float* w_restore = (const float*)d_in[6];
    const float* bn_gamma  = (const float*)d_in[7];
    const float* bn_beta   = (const float*)d_in[8];
    // d_in[9]=src, d_in[10]=dst : fixed 4-neighbor grid + self loops (implicit)
    float* out = (float*)d_out;

    // Idempotent, deterministic, not stream-ordered: safe under graph capture,
    // no static guards (harness forbids call-count-dependent behavior).
    cudaFuncSetAttribute(kB12, cudaFuncAttributeMaxDynamicSharedMemorySize,
                         SM_FLOATS * (int)sizeof(float));

    kA<<<TOT/128, 256>>>(x, w_reduce, w_lin, att_src, att_dst, b_gat, w_restore);
    kB12<<<TOT/WDIM, 256, SM_FLOATS*sizeof(float)>>>(x);
    kD<<<(size_t)(TOT)*COUTC/(256*4), 256>>>(bn_gamma, bn_beta, out);
}

// round 12
// speedup vs baseline: 1.3291x; 1.0312x over previous
#include <cuda_runtime.h>
#include <math.h>

#define BATCH 8
#define CINC 64
#define COUTC 64
#define HDIM 128
#define WDIM 128
#define NPIX (HDIM*WDIM)          // 16384
#define NHEADS 4
#define CRED 32
#define TOT (BATCH*NPIX)          // 131072
#define KDIM (NHEADS*CRED)        // 128

typedef unsigned long long u64;

// packed fp32x2 helpers (Blackwell FFMA2 — only reachable via PTX)
#define FMA2(acc, a, b) \
    asm("fma.rn.f32x2 %0, %1, %2, %0;" : "+l"(acc) : "l"(a), "l"(b))
#define PACK_DUP(dst, f) \
    asm("mov.b64 %0, {%1, %1};" : "=l"(dst) : "r"(__float_as_uint(f)))
#define UNPACK2(lo, hi, src) \
    asm("mov.b64 {%0, %1}, %2;" : "=r"(lo), "=r"(hi) : "l"(src))

// -------- device scratch (no allocation allowed in kernel_launch) --------
__device__ float g_xr[(size_t)TOT*CRED];            // [B*N][32] node-major
__device__ float g_as[(size_t)TOT*NHEADS];
__device__ float g_ad[(size_t)TOT*NHEADS];
__device__ float g_out[(size_t)TOT*COUTC];          // [B][64][N] channel-major
__device__ float g_M[COUTC*KDIM];                   // [o][k] row-major
__device__ float g_wrb[COUTC];
__device__ float g_chsum[COUTC];
__device__ float g_chsq[COUTC];

// ------------- A: xr = W @ x as a register-tiled GEMM + logits -----------
// Block = 128 pixels. GEMM thread tile 4c x 4p. xrT OVERLAYS xs (disjoint
// live ranges, separated by barriers) -> smem 44 KB; launch_bounds(256,4)
// caps regs at 64 -> 4 CTAs/SM (occ 50%, was 32%).
__global__ void __launch_bounds__(256, 4) kA(const float* __restrict__ x,
                                             const float* __restrict__ w_reduce,
                                             const float* __restrict__ w_lin,
                                             const float* __restrict__ att_src,
                                             const float* __restrict__ att_dst,
                                             const float* __restrict__ b_gat,
                                             const float* __restrict__ w_restore) {
    __shared__ __align__(16) float xs[64*132];   // x tile; later xrT[128][44]
    __shared__ __align__(16) float ws[64*36];    // W^T [cin][32c]
    __shared__ __align__(16) float pqs[2*NHEADS*CRED];
    float* xrT = xs;                             // overlay

    int t = threadIdx.x;
    int b = blockIdx.x >> 7;
    int pix0 = (blockIdx.x & 127) << 7;

    for (int f = t; f < CRED*CINC; f += 256) {
        int c = f >> 6, cin = f & 63;
        ws[cin*36 + c] = w_reduce[f];
    }
    {   // pq per block: pq[h][c] = (W_h^T att)[c]
        int which = t >> 7;
        int hc = t & 127;
        int h = hc >> 5, c = hc & 31;
        const float* att = which ? att_dst : att_src;
        float s = 0.f;
        #pragma unroll 8
        for (int cr = 0; cr < CRED; cr++)
            s += att[h*CRED+cr] * w_lin[(h*CRED+cr)*CRED + c];
        pqs[t] = s;
    }
    if (blockIdx.x == 0) {   // folded kP: M, wrb, BN-acc zero
        for (int idx = t; idx < COUTC*KDIM; idx += 256) {
            int o = idx >> 7, k = idx & 127, h = k >> 5, c = k & 31;
            float s = 0.f;
            #pragma unroll 8
            for (int cr = 0; cr < CRED; cr++)
                s += w_restore[o*CRED+cr] * w_lin[(h*CRED+cr)*CRED + c];
            g_M[idx] = 0.25f * s;
        }
        if (t < COUTC) {
            float s = 0.f;
            #pragma unroll 8
            for (int c = 0; c < CRED; c++) s += w_restore[t*CRED+c] * b_gat[c];
            g_wrb[t] = s;
            g_chsum[t] = 0.f;
            g_chsq[t]  = 0.f;
        }
    }
    {   // stage x tile [64 cin][128 p]
        const float* xb = x + (((size_t)b*CINC) << 14) + pix0;
        for (int f = t; f < 2048; f += 256) {
            int cin = f >> 5, p4 = f & 31;
            *(float4*)&xs[cin*132 + 4*p4] =
                *(const float4*)&xb[(((size_t)cin) << 14) + 4*p4];
        }
    }
    __syncthreads();

    // ---- GEMM 32x128x64: thread tile 4c x 4p ----
    int po = t & 31, co = t >> 5;
    int p0 = 4*po, c0 = 4*co;
    u64 acc2[2][4];
    #pragma unroll
    for (int a0 = 0; a0 < 2; a0++)
        #pragma unroll
        for (int a1 = 0; a1 < 4; a1++) acc2[a0][a1] = 0ull;

    #pragma unroll 4
    for (int cin = 0; cin < CINC; cin++) {
        ulonglong2 wv = *(const ulonglong2*)&ws[cin*36 + c0];  // broadcast
        float4 xv = *(const float4*)&xs[cin*132 + p0];
        u64 xp[4];
        PACK_DUP(xp[0], xv.x); PACK_DUP(xp[1], xv.y);
        PACK_DUP(xp[2], xv.z); PACK_DUP(xp[3], xv.w);
        #pragma unroll
        for (int ip = 0; ip < 4; ip++) {
            FMA2(acc2[0][ip], wv.x, xp[ip]);
            FMA2(acc2[1][ip], wv.y, xp[ip]);
        }
    }
    __syncthreads();    // xs fully consumed -> xrT overlay becomes safe

    #pragma unroll
    for (int ip = 0; ip < 4; ip++) {
        unsigned l0, h0, l1, h1;
        UNPACK2(l0, h0, acc2[0][ip]);
        UNPACK2(l1, h1, acc2[1][ip]);
        *(float4*)&xrT[(p0+ip)*44 + c0] =
            make_float4(__uint_as_float(l0), __uint_as_float(h0),
                        __uint_as_float(l1), __uint_as_float(h1));
    }
    __syncthreads();

    // ---- logits: 2 threads per pixel ----
    {
        int px = t & 127, half = t >> 7;
        const float* pqh = pqs + half*128;
        float a0 = 0.f, a1 = 0.f, a2 = 0.f, a3 = 0.f;
        #pragma unroll
        for (int k = 0; k < 8; k++) {
            float4 xv = *(const float4*)&xrT[px*44 + 4*k];
            int cb = 4*k;
            a0 += pqh[0*CRED+cb]*xv.x + pqh[0*CRED+cb+1]*xv.y
                + pqh[0*CRED+cb+2]*xv.z + pqh[0*CRED+cb+3]*xv.w;
            a1 += pqh[1*CRED+cb]*xv.x + pqh[1*CRED+cb+1]*xv.y
                + pqh[1*CRED+cb+2]*xv.z + pqh[1*CRED+cb+3]*xv.w;
            a2 += pqh[2*CRED+cb]*xv.x + pqh[2*CRED+cb+1]*xv.y
                + pqh[2*CRED+cb+2]*xv.z + pqh[2*CRED+cb+3]*xv.w;
            a3 += pqh[3*CRED+cb]*xv.x + pqh[3*CRED+cb+1]*xv.y
                + pqh[3*CRED+cb+2]*xv.z + pqh[3*CRED+cb+3]*xv.w;
        }
        size_t node = ((size_t)b << 14) + pix0 + px;
        float* dst = half ? g_ad : g_as;
        *(float4*)&dst[node*NHEADS] = make_float4(a0, a1, a2, a3);
    }
    // ---- xr writeback: full 128B lines ----
    {
        int gpix = (b << 14) + pix0;
        for (int f = t; f < 1024; f += 256) {
            int px = f >> 3, k = f & 7;
            *(float4*)&g_xr[((size_t)(gpix+px))*CRED + 4*k] =
                *(const float4*)&xrT[px*44 + 4*k];
        }
    }
}

// ====== B12: fused GAT aggregation + restore GEMM + residual + BN-stats ==
// HALF-ROW tiles (64 px) -> smem 74.2 KB -> 3 CTAs/SM (occ 37.5%, was 25%).
// Phase 2a computes each node's softmax once -> normalized alpha (overlaid
// on the Ms region); 2b does weighted sums with broadcast alpha; Ms staged
// after the overlay dies; phase 3 = packed-FFMA2 GEMM 64o x 64p x 128k.
//
// smem (floats): Ms[128][68] @0 (8704, Al overlay 64*20=1280)
//                Ss[128][68] @8704 (8704)
//                As3[3][68][4] @17408 (816)   a_src rows, j0-1..j0+64
//                Ad4[64][4] @18224 (256)
//                wrb[64] @18480 (64)
// total 18544 floats = 74176 B (x3 = 222.5 KB)
#define SMB_MS   0
#define SMB_SS   8704
#define SMB_AS   17408
#define SMB_AD   18224
#define SMB_WRB  18480
#define SMB_FLOATS 18544

__global__ void __launch_bounds__(256, 3) kB12(const float* __restrict__ x) {
    extern __shared__ __align__(16) float sm[];
    float* Ms  = sm + SMB_MS;
    float* Al  = sm + SMB_MS;             // overlay: alpha [jl][u][h]
    float* Ss  = sm + SMB_SS;
    float* As3 = sm + SMB_AS;
    float* Ad4 = sm + SMB_AD;
    float* wrbs= sm + SMB_WRB;

    int t = threadIdx.x;
    int b   = blockIdx.x >> 8;
    int rem = blockIdx.x & 255;
    int i   = rem >> 1;                   // grid row
    int j0  = (rem & 1) << 6;             // 0 or 64
    int gbase = b << 14;

    // ---- stage a_src rows i-1,i,i+1 for j in [j0-1, j0+64] (66 cols) ----
    if (t < 198) {
        int r = t / 66, jj = t - r*66;
        int gi = i - 1 + r;
        int jg = j0 - 1 + jj;
        float4 v = make_float4(0.f,0.f,0.f,0.f);
        if (gi >= 0 && gi < HDIM && jg >= 0 && jg < WDIM)
            v = *(const float4*)&g_as[((size_t)(gbase + gi*WDIM + jg))*NHEADS];
        *(float4*)&As3[(r*68 + jj)*4] = v;
    }
    if (t < 64)
        *(float4*)&Ad4[t*4] =
            *(const float4*)&g_ad[((size_t)(gbase + i*WDIM + j0 + t))*NHEADS];
    __syncthreads();

    // ---- phase 2a: per-(node,head) softmax ONCE -> Al (256 pairs) ----
    {
        int jl = t & 63, h = t >> 6;
        int jglob = j0 + jl;
        int jc = jl + 1;                  // As3 col of self
        bool vl[5] = {true, (i > 0), (i < HDIM-1), (jglob > 0), (jglob < WDIM-1)};
        int  rr[5] = {1, 0, 2, 1, 1};
        int  cc[5] = {jc, jc, jc, jc-1, jc+1};
        float adh = Ad4[jl*4 + h];
        float ex[5]; float d = 0.f;
        #pragma unroll
        for (int u = 0; u < 5; u++) {
            float ev = As3[(rr[u]*68 + cc[u])*4 + h] + adh;
            ev = ev > 0.f ? ev : 0.2f*ev;            // leaky_relu(0.2)
            float xx = vl[u] ? __expf(ev) : 0.f;     // shift-free, |logit| small
            ex[u] = xx; d += xx;
        }
        float rd = 1.f / d;
        #pragma unroll
        for (int u = 0; u < 5; u++)
            Al[jl*20 + u*4 + h] = ex[u] * rd;
    }
    __syncthreads();

    // ---- phase 2b: weighted neighbor sums -> Ss[k][p] ----
    {
        int w = t >> 5, lane = t & 31;
        for (int jb = 0; jb < 2; jb++) {
            float sjh[NHEADS][4];
            #pragma unroll
            for (int jq = 0; jq < 4; jq++) {
                int jl = w*8 + jb*4 + jq;
                int jglob = j0 + jl;
                bool vl[5] = {true, (i > 0), (i < HDIM-1),
                              (jglob > 0), (jglob < WDIM-1)};
                int gi[5] = {i, i-1, i+1, i, i};
                int gj[5] = {jglob, jglob, jglob,
                             (jglob>0? jglob-1 : jglob),
                             (jglob<WDIM-1? jglob+1 : jglob)};
                float xv[5];
                #pragma unroll
                for (int u = 0; u < 5; u++)
                    xv[u] = vl[u]
                        ? g_xr[((size_t)(gbase + gi[u]*WDIM + gj[u]))*CRED + lane]
                        : 0.f;
                float4 al[5];
                #pragma unroll
                for (int u = 0; u < 5; u++)
                    al[u] = *(const float4*)&Al[jl*20 + u*4];
                float s0 = 0.f, s1 = 0.f, s2 = 0.f, s3 = 0.f;
                #pragma unroll
                for (int u = 0; u < 5; u++) {
                    s0 += al[u].x * xv[u];
                    s1 += al[u].y * xv[u];
                    s2 += al[u].z * xv[u];
                    s3 += al[u].w * xv[u];
                }
                sjh[0][jq] = s0; sjh[1][jq] = s1;
                sjh[2][jq] = s2; sjh[3][jq] = s3;
            }
            int jl0 = w*8 + jb*4;
            #pragma unroll
            for (int h = 0; h < NHEADS; h++)
                *(float4*)&Ss[(h*CRED + lane)*68 + jl0] =
                    make_float4(sjh[h][0], sjh[h][1], sjh[h][2], sjh[h][3]);
        }
    }
    __syncthreads();

    // ---- stage M (transposed) and wrb (alpha overlay now dead) ----
    for (int f = t; f < COUTC*KDIM; f += 256)
        Ms[(f & 127)*68 + (f >> 7)] = g_M[f];
    if (t < COUTC) wrbs[t] = g_wrb[t];
    __syncthreads();

    // ---- phase 3: GEMM 64o x 64p x 128k via packed FFMA2 ----
    int po = t & 15, oo = t >> 4;
    int p0 = 4*po, o0 = 4*oo;
    u64 acc2[2][4];
    #pragma unroll
    for (int a0 = 0; a0 < 2; a0++)
        #pragma unroll
        for (int a1 = 0; a1 < 4; a1++) acc2[a0][a1] = 0ull;

    #pragma unroll 1
    for (int k0 = 0; k0 < KDIM; k0 += 8) {
        #pragma unroll
        for (int kk = 0; kk < 8; kk++) {
            int k = k0 + kk;
            ulonglong2 mv = *(const ulonglong2*)&Ms[k*68 + o0];
            float4 sv = *(const float4*)&Ss[k*68 + p0];
            u64 sp[4];
            PACK_DUP(sp[0], sv.x); PACK_DUP(sp[1], sv.y);
            PACK_DUP(sp[2], sv.z); PACK_DUP(sp[3], sv.w);
            #pragma unroll
            for (int ip = 0; ip < 4; ip++) {
                FMA2(acc2[0][ip], mv.x, sp[ip]);
                FMA2(acc2[1][ip], mv.y, sp[ip]);
            }
        }
    }

    float acc[4][4];
    #pragma unroll
    for (int op = 0; op < 2; op++)
        #pragma unroll
        for (int ip = 0; ip < 4; ip++) {
            unsigned lo, hi; UNPACK2(lo, hi, acc2[op][ip]);
            acc[2*op][ip]   = __uint_as_float(lo);
            acc[2*op+1][ip] = __uint_as_float(hi);
        }

    // ---- epilogue: +wrb +residual, store, BN partial sums ----
    float csum[4], csq[4];
    #pragma unroll
    for (int io = 0; io < 4; io++) {
        int o = o0 + io;
        size_t off = (((size_t)b*COUTC + o) << 14) + i*WDIM + j0 + p0;
        float4 xv = *(const float4*)&x[off];
        float wb = wrbs[o];
        float4 r;
        r.x = acc[io][0] + wb + xv.x;
        r.y = acc[io][1] + wb + xv.y;
        r.z = acc[io][2] + wb + xv.z;
        r.w = acc[io][3] + wb + xv.w;
        *(float4*)&g_out[off] = r;
        csum[io] = r.x + r.y + r.z + r.w;
        csq[io]  = r.x*r.x + r.y*r.y + r.z*r.z + r.w*r.w;
    }
    // channels o0..o0+3 owned by the 16 po-threads of this oo group
    #pragma unroll
    for (int io = 0; io < 4; io++) {
        #pragma unroll
        for (int off = 8; off > 0; off >>= 1) {
            csum[io] += __shfl_down_sync(0xffffffffu, csum[io], off, 16);
            csq[io]  += __shfl_down_sync(0xffffffffu, csq[io],  off, 16);
        }
    }
    if (po == 0) {
        #pragma unroll
        for (int io = 0; io < 4; io++) {
            atomicAdd(&g_chsum[o0+io], csum[io]);
            atomicAdd(&g_chsq[o0+io],  csq[io]);
        }
    }
}

// ------------------ D: normalize + affine + relu -------------------------
__global__ void __launch_bounds__(256) kD(const float* __restrict__ gamma,
                                          const float* __restrict__ beta,
                                          float* __restrict__ out) {
    size_t e4 = (size_t)blockIdx.x * 256 + threadIdx.x;
    size_t e = e4 * 4;
    int c = (int)((e >> 14) & 63);
    const float invcnt = 1.f / (float)(BATCH*NPIX);
    float mean = g_chsum[c] * invcnt;
    float var  = g_chsq[c] * invcnt - mean*mean;
    float inv  = rsqrtf(var + 1e-5f) * gamma[c];
    float sh   = beta[c] - mean * inv;
    float4 v = *(const float4*)&g_out[e];
    float4 r;
    r.x = fmaxf(v.x*inv + sh, 0.f);
    r.y = fmaxf(v.y*inv + sh, 0.f);
    r.z = fmaxf(v.z*inv + sh, 0.f);
    r.w = fmaxf(v.w*inv + sh, 0.f);
    *(float4*)&out[e] = r;
}

// -------------------------------------------------------------------------
extern "C" void kernel_launch(void* const* d_in, const int* in_sizes, int n_in,
                              void* d_out, int out_size) {
    const float* x         = (const float*)d_in[0];
    const float* w_reduce  = (const float*)d_in[1];
    const float* w_lin     = (const float*)d_in[2];
    const float* att_src   = (const float*)d_in[3];
    const float* att_dst   = (const float*)d_in[4];
    const float* b_gat     = (const float*)d_in[5];
    const float* w_restore = (const float*)d_in[6];
    const float* bn_gamma  = (const float*)d_in[7];
    const float* bn_beta   = (const float*)d_in[8];
    float* out = (float*)d_out;

    cudaFuncSetAttribute(kB12, cudaFuncAttributeMaxDynamicSharedMemorySize,
                         SMB_FLOATS * (int)sizeof(float));

    kA<<<TOT/128, 256>>>(x, w_reduce, w_lin, att_src, att_dst, b_gat, w_restore);
    kB12<<<TOT/64, 256, SMB_FLOATS*sizeof(float)>>>(x);
    kD<<<(size_t)(TOT)*COUTC/(256*4), 256>>>(bn_gamma, bn_beta, out);
}